// round 1
// baseline (speedup 1.0000x reference)
#include <cuda_runtime.h>
#include <math.h>

#define Bb 16
#define Nn 1024
#define Tt 512
#define Cc 768
#define ROWS1 (Bb*Tt)   // 8192
#define ROWS2 (Bb*Nn)   // 16384

// ---------------- device scratch (no allocations allowed) ----------------
__device__ float g_e1[(size_t)ROWS1*Cc];        // text_emb (raw GEMM, then BN+relu in place)
__device__ float g_v [(size_t)ROWS1*Cc];        // v = text@Wout^T + bout
__device__ float g_attn[(size_t)Bb*Tt*Nn];      // attn_t[B,T,N], then masked softmax w in place
__device__ float g_p1[64 * 2 * Cc];             // BN1 partial sums/sumsq
__device__ float g_p2[128 * 2 * Cc];            // BN2 partial sums/sumsq
__device__ float g_mu1[Cc], g_rs1[Cc], g_mu2[Cc], g_rs2[Cc];

// ---------------- NT SGEMM: C[M,N] = alpha * A[M,K] @ B[N,K]^T (+bias[n]) ----------------
__global__ __launch_bounds__(256) void sgemm_nt(
    const float* __restrict__ A, const float* __restrict__ B, float* __restrict__ C,
    int M, int N, int K, long sA, long sB, long sC,
    const float* __restrict__ bias, float alpha)
{
    A += (long)blockIdx.z * sA;
    B += (long)blockIdx.z * sB;
    C += (long)blockIdx.z * sC;
    const int m0 = blockIdx.y * 128, n0 = blockIdx.x * 128;
    __shared__ __align__(16) float As[16][132];
    __shared__ __align__(16) float Bs[16][132];
    const int tid = threadIdx.x;
    const int tx = tid & 15, ty = tid >> 4;
    float acc[8][8] = {};
    for (int k0 = 0; k0 < K; k0 += 16) {
#pragma unroll
        for (int i = 0; i < 2; i++) {
            int idx = tid * 2 + i;            // 0..511 float4 slots
            int r = idx >> 2;                 // 0..127 tile row
            int c4 = (idx & 3) * 4;           // 0,4,8,12
            float4 a = *reinterpret_cast<const float4*>(A + (long)(m0 + r) * K + k0 + c4);
            As[c4+0][r] = a.x; As[c4+1][r] = a.y; As[c4+2][r] = a.z; As[c4+3][r] = a.w;
            float4 b = *reinterpret_cast<const float4*>(B + (long)(n0 + r) * K + k0 + c4);
            Bs[c4+0][r] = b.x; Bs[c4+1][r] = b.y; Bs[c4+2][r] = b.z; Bs[c4+3][r] = b.w;
        }
        __syncthreads();
#pragma unroll
        for (int kk = 0; kk < 16; kk++) {
            float a[8], b[8];
#pragma unroll
            for (int i = 0; i < 8; i++) a[i] = As[kk][ty*8 + i];
#pragma unroll
            for (int j = 0; j < 8; j++) b[j] = Bs[kk][tx*8 + j];
#pragma unroll
            for (int i = 0; i < 8; i++)
#pragma unroll
                for (int j = 0; j < 8; j++)
                    acc[i][j] = fmaf(a[i], b[j], acc[i][j]);
        }
        __syncthreads();
    }
#pragma unroll
    for (int i = 0; i < 8; i++) {
        long row = m0 + ty*8 + i;
#pragma unroll
        for (int j4 = 0; j4 < 2; j4++) {
            int col = n0 + tx*8 + j4*4;
            float4 o;
            o.x = acc[i][j4*4+0] * alpha;
            o.y = acc[i][j4*4+1] * alpha;
            o.z = acc[i][j4*4+2] * alpha;
            o.w = acc[i][j4*4+3] * alpha;
            if (bias) { o.x += bias[col]; o.y += bias[col+1]; o.z += bias[col+2]; o.w += bias[col+3]; }
            *reinterpret_cast<float4*>(C + row * N + col) = o;
        }
    }
}

// ---------------- TN SGEMM: C[M,N] = A[K,M]^T @ B[K,N] ----------------
__global__ __launch_bounds__(256) void sgemm_tn(
    const float* __restrict__ A, const float* __restrict__ B, float* __restrict__ C,
    int M, int N, int K, long sA, long sB, long sC)
{
    A += (long)blockIdx.z * sA;
    B += (long)blockIdx.z * sB;
    C += (long)blockIdx.z * sC;
    const int m0 = blockIdx.y * 128, n0 = blockIdx.x * 128;
    __shared__ __align__(16) float As[16][132];
    __shared__ __align__(16) float Bs[16][132];
    const int tid = threadIdx.x;
    const int tx = tid & 15, ty = tid >> 4;
    float acc[8][8] = {};
    for (int k0 = 0; k0 < K; k0 += 16) {
#pragma unroll
        for (int i = 0; i < 2; i++) {
            int idx = tid * 2 + i;            // 0..511
            int r = idx >> 5;                 // 16 rows, 32 float4 per row
            int c = (idx & 31) * 4;           // 0..124
            *reinterpret_cast<float4*>(&As[r][c]) =
                *reinterpret_cast<const float4*>(A + (long)(k0 + r) * M + m0 + c);
            *reinterpret_cast<float4*>(&Bs[r][c]) =
                *reinterpret_cast<const float4*>(B + (long)(k0 + r) * N + n0 + c);
        }
        __syncthreads();
#pragma unroll
        for (int kk = 0; kk < 16; kk++) {
            float a[8], b[8];
#pragma unroll
            for (int i = 0; i < 8; i++) a[i] = As[kk][ty*8 + i];
#pragma unroll
            for (int j = 0; j < 8; j++) b[j] = Bs[kk][tx*8 + j];
#pragma unroll
            for (int i = 0; i < 8; i++)
#pragma unroll
                for (int j = 0; j < 8; j++)
                    acc[i][j] = fmaf(a[i], b[j], acc[i][j]);
        }
        __syncthreads();
    }
#pragma unroll
    for (int i = 0; i < 8; i++) {
        long row = m0 + ty*8 + i;
#pragma unroll
        for (int j4 = 0; j4 < 2; j4++) {
            int col = n0 + tx*8 + j4*4;
            float4 o;
            o.x = acc[i][j4*4+0]; o.y = acc[i][j4*4+1];
            o.z = acc[i][j4*4+2]; o.w = acc[i][j4*4+3];
            *reinterpret_cast<float4*>(C + row * N + col) = o;
        }
    }
}

// ---------------- per-(b,t) column: softmax stats + K-th-largest radix select + masked write ----------------
__global__ __launch_bounds__(256) void topk_softmax(const float* __restrict__ kvals)
{
    const int b = blockIdx.x >> 9;        // /512
    const int t = blockIdx.x & 511;
    float* col = g_attn + ((long)b * Tt + t) * Nn;
    const int tid = threadIdx.x;
    __shared__ float sh[8];
    __shared__ unsigned hist[256];
    __shared__ unsigned s_sel, s_rem;

    float x[4]; unsigned u[4];
    float mx = -3.4e38f;
#pragma unroll
    for (int i = 0; i < 4; i++) {
        x[i] = col[tid + 256*i];
        mx = fmaxf(mx, x[i]);
        unsigned bits = __float_as_uint(x[i]);
        u[i] = (bits & 0x80000000u) ? ~bits : (bits | 0x80000000u);  // order-preserving map
    }
    // block max
    for (int o = 16; o > 0; o >>= 1) mx = fmaxf(mx, __shfl_xor_sync(0xffffffffu, mx, o));
    if ((tid & 31) == 0) sh[tid >> 5] = mx;
    __syncthreads();
    if (tid == 0) { float m = sh[0]; for (int i = 1; i < 8; i++) m = fmaxf(m, sh[i]); sh[0] = m; }
    __syncthreads();
    mx = sh[0];
    __syncthreads();
    // block sum of exp
    float s = 0.f;
#pragma unroll
    for (int i = 0; i < 4; i++) s += expf(x[i] - mx);
    for (int o = 16; o > 0; o >>= 1) s += __shfl_xor_sync(0xffffffffu, s, o);
    if ((tid & 31) == 0) sh[tid >> 5] = s;
    __syncthreads();
    if (tid == 0) { float m = 0.f; for (int i = 0; i < 8; i++) m += sh[i]; sh[0] = m; }
    __syncthreads();
    const float inv = 1.f / sh[0];

    int K = (int)rintf((float)Nn * kvals[b]);
    if (K < 0) K = 0;
    if (K > Nn) K = Nn;
    if (K == 0) {
#pragma unroll
        for (int i = 0; i < 4; i++) col[tid + 256*i] = 0.f;
        return;
    }
    unsigned thr = 0u;
    if (K < Nn) {
        unsigned pref = 0u, rem = (unsigned)K;
        for (int shift = 24; shift >= 0; shift -= 8) {
            hist[tid] = 0u;
            __syncthreads();
            unsigned hm = (shift == 24) ? 0u : (0xFFFFFFFFu << (shift + 8));
#pragma unroll
            for (int i = 0; i < 4; i++)
                if ((u[i] & hm) == pref) atomicAdd(&hist[(u[i] >> shift) & 255u], 1u);
            __syncthreads();
            // inclusive suffix sum (Hillis-Steele)
            for (int off = 1; off < 256; off <<= 1) {
                unsigned vv = (tid + off < 256) ? hist[tid + off] : 0u;
                __syncthreads();
                hist[tid] += vv;
                __syncthreads();
            }
            unsigned nxt = (tid < 255) ? hist[tid + 1] : 0u;
            if (hist[tid] >= rem && nxt < rem) { s_sel = (unsigned)tid; s_rem = rem - nxt; }
            __syncthreads();
            pref |= (s_sel << shift);
            rem = s_rem;
            __syncthreads();
        }
        thr = pref;   // exact K-th largest as ordered uint
    }
#pragma unroll
    for (int i = 0; i < 4; i++) {
        float w = (u[i] >= thr) ? expf(x[i] - mx) * inv : 0.f;
        col[tid + 256*i] = w;
    }
}

// ---------------- BN stats: deterministic two-stage reduction ----------------
__global__ __launch_bounds__(256) void bn_partial(const float* __restrict__ X, float* __restrict__ part)
{
    const int tid = threadIdx.x;
    const float* base = X + (long)blockIdx.x * 128 * Cc;
    float s0=0,s1=0,s2=0,q0=0,q1=0,q2=0;
    for (int r = 0; r < 128; r++) {
        const float* row = base + (long)r * Cc;
        float a = row[tid], b = row[tid+256], c = row[tid+512];
        s0 += a; q0 = fmaf(a,a,q0);
        s1 += b; q1 = fmaf(b,b,q1);
        s2 += c; q2 = fmaf(c,c,q2);
    }
    float* p = part + (long)blockIdx.x * (2*Cc);
    p[tid]      = s0; p[tid+256]      = s1; p[tid+512]      = s2;
    p[Cc+tid]   = q0; p[Cc+tid+256]   = q1; p[Cc+tid+512]   = q2;
}

__global__ void bn_finalize(const float* __restrict__ part, int nblk, float invN,
                            float* __restrict__ mu, float* __restrict__ rs)
{
    int c = blockIdx.x * 256 + threadIdx.x;
    if (c >= Cc) return;
    float s = 0.f, q = 0.f;
    for (int i = 0; i < nblk; i++) {
        s += part[(long)i * 2 * Cc + c];
        q += part[(long)i * 2 * Cc + Cc + c];
    }
    float m = s * invN;
    mu[c] = m;
    rs[c] = rsqrtf(q * invN - m * m + 1e-5f);
}

// ---------------- elementwise BN apply ----------------
__global__ __launch_bounds__(256) void bn1_apply(const float* __restrict__ g, const float* __restrict__ bb)
{
    int i4 = blockIdx.x * 256 + threadIdx.x;   // over ROWS1*Cc/4
    float4* p = reinterpret_cast<float4*>(g_e1);
    float4 y = p[i4];
    int c = (i4 * 4) % Cc;
    y.x = fmaxf(g[c+0]*(y.x - g_mu1[c+0])*g_rs1[c+0] + bb[c+0], 0.f);
    y.y = fmaxf(g[c+1]*(y.y - g_mu1[c+1])*g_rs1[c+1] + bb[c+1], 0.f);
    y.z = fmaxf(g[c+2]*(y.z - g_mu1[c+2])*g_rs1[c+2] + bb[c+2], 0.f);
    y.w = fmaxf(g[c+3]*(y.w - g_mu1[c+3])*g_rs1[c+3] + bb[c+3], 0.f);
    p[i4] = y;
}

__global__ __launch_bounds__(256) void final_apply(float* __restrict__ out, const float* __restrict__ img,
                                                   const float* __restrict__ g, const float* __restrict__ bb)
{
    int i4 = blockIdx.x * 256 + threadIdx.x;   // over ROWS2*Cc/4
    float4 o = reinterpret_cast<float4*>(out)[i4];
    float4 im = reinterpret_cast<const float4*>(img)[i4];
    int c = (i4 * 4) % Cc;
    o.x = fmaxf(g[c+0]*(o.x - g_mu2[c+0])*g_rs2[c+0] + bb[c+0], 0.f) + im.x;
    o.y = fmaxf(g[c+1]*(o.y - g_mu2[c+1])*g_rs2[c+1] + bb[c+1], 0.f) + im.y;
    o.z = fmaxf(g[c+2]*(o.z - g_mu2[c+2])*g_rs2[c+2] + bb[c+2], 0.f) + im.z;
    o.w = fmaxf(g[c+3]*(o.w - g_mu2[c+3])*g_rs2[c+3] + bb[c+3], 0.f) + im.w;
    reinterpret_cast<float4*>(out)[i4] = o;
}

// ---------------- orchestration ----------------
extern "C" void kernel_launch(void* const* d_in, const int* in_sizes, int n_in,
                              void* d_out, int out_size)
{
    (void)in_sizes; (void)n_in; (void)out_size;
    const float* image = (const float*)d_in[0];
    const float* text  = (const float*)d_in[1];
    const float* kv    = (const float*)d_in[2];
    const float* Wc    = (const float*)d_in[3];
    const float* bc    = (const float*)d_in[4];
    const float* g1    = (const float*)d_in[5];
    const float* b1    = (const float*)d_in[6];
    const float* Wout  = (const float*)d_in[7];
    const float* bout  = (const float*)d_in[8];
    const float* g2    = (const float*)d_in[9];
    const float* b2    = (const float*)d_in[10];
    float* out = (float*)d_out;

    float *e1, *v, *attn, *p1, *p2, *mu1, *rs1, *mu2, *rs2;
    cudaGetSymbolAddress((void**)&e1,  g_e1);
    cudaGetSymbolAddress((void**)&v,   g_v);
    cudaGetSymbolAddress((void**)&attn,g_attn);
    cudaGetSymbolAddress((void**)&p1,  g_p1);
    cudaGetSymbolAddress((void**)&p2,  g_p2);
    cudaGetSymbolAddress((void**)&mu1, g_mu1);
    cudaGetSymbolAddress((void**)&rs1, g_rs1);
    cudaGetSymbolAddress((void**)&mu2, g_mu2);
    cudaGetSymbolAddress((void**)&rs2, g_rs2);

    // 1) y1 = text @ Wc^T + bc   [8192,768]
    sgemm_nt<<<dim3(Cc/128, ROWS1/128, 1), 256>>>(text, Wc, e1, ROWS1, Cc, Cc, 0, 0, 0, bc, 1.f);
    // 2) v = text @ Wout^T + bout
    sgemm_nt<<<dim3(Cc/128, ROWS1/128, 1), 256>>>(text, Wout, v, ROWS1, Cc, Cc, 0, 0, 0, bout, 1.f);
    // 3) BN1 stats
    bn_partial<<<ROWS1/128, 256>>>(e1, p1);
    bn_finalize<<<3, 256>>>(p1, ROWS1/128, 1.f/(float)ROWS1, mu1, rs1);
    // 4) e1 = relu(BN(y1)) in place
    bn1_apply<<<(ROWS1*Cc/4)/256, 256>>>(g1, b1);
    // 5) attn_t[b,t,n] = (e1[b] @ image[b]^T) / sqrt(C)   (batched NT)
    sgemm_nt<<<dim3(Nn/128, Tt/128, Bb), 256>>>(e1, image, attn,
                                                Tt, Nn, Cc,
                                                (long)Tt*Cc, (long)Nn*Cc, (long)Tt*Nn,
                                                nullptr, 1.f/sqrtf((float)Cc));
    // 6) per-column masked softmax weights in place
    topk_softmax<<<Bb*Tt, 256>>>(kv);
    // 7) out_pre[b,n,c] = sum_t w[b,t,n] * v[b,t,c]   (batched TN) -> d_out
    sgemm_tn<<<dim3(Cc/128, Nn/128, Bb), 256>>>(attn, v, out,
                                                Nn, Cc, Tt,
                                                (long)Tt*Nn, (long)Tt*Cc, (long)Nn*Cc);
    // 8) BN2 stats over out_pre
    bn_partial<<<ROWS2/128, 256>>>(out, p2);
    bn_finalize<<<3, 256>>>(p2, ROWS2/128, 1.f/(float)ROWS2, mu2, rs2);
    // 9) out = relu(BN(out_pre)) + image, in place
    final_apply<<<(ROWS2*Cc/4)/256, 256>>>(out, image, g2, b2);
}

// round 3
// speedup vs baseline: 1.9216x; 1.9216x over previous
#include <cuda_runtime.h>
#include <cuda_bf16.h>
#include <cstdint>
#include <math.h>

#define Bb 16
#define Nn 1024
#define Tt 512
#define Cc 768
#define ROWS1 (Bb*Tt)   // 8192
#define ROWS2 (Bb*Nn)   // 16384

typedef unsigned short ushrt;

// ---------------- device scratch ----------------
__device__ float g_y1[(size_t)ROWS1*Cc];        // text@Wc^T (pre-BN)
__device__ float g_attn[(size_t)Bb*Tt*Nn];      // attn_t[B,T,N] -> masked softmax w in place
__device__ float g_vt[(size_t)Bb*Cc*Tt];        // vT[b][c,t] fp32
__device__ float g_p1[64*2*Cc];
__device__ float g_p2[128*2*Cc];
__device__ float g_mu1[Cc], g_rs1[Cc], g_mu2[Cc], g_rs2[Cc];

// packed bf16 hi/lo operands, plain row-major [rows][K]
__device__ ushrt p_text_hi[(size_t)ROWS1*Cc], p_text_lo[(size_t)ROWS1*Cc];
__device__ ushrt p_img_hi [(size_t)ROWS2*Cc], p_img_lo [(size_t)ROWS2*Cc];
__device__ ushrt p_Wc_hi[Cc*Cc], p_Wc_lo[Cc*Cc];
__device__ ushrt p_Wo_hi[Cc*Cc], p_Wo_lo[Cc*Cc];
__device__ ushrt p_e1_hi[(size_t)ROWS1*Cc], p_e1_lo[(size_t)ROWS1*Cc];
__device__ ushrt p_vt_hi[(size_t)Bb*Cc*Tt], p_vt_lo[(size_t)Bb*Cc*Tt];
__device__ ushrt p_wt_hi[(size_t)Bb*Nn*Tt], p_wt_lo[(size_t)Bb*Nn*Tt];

// ---------------- helpers ----------------
__device__ __forceinline__ uint32_t smem_u32(const void* p) {
    uint32_t a;
    asm("{ .reg .u64 t; cvta.to.shared.u64 t, %1; cvt.u32.u64 %0, t; }" : "=r"(a) : "l"(p));
    return a;
}
__device__ __forceinline__ void cpa16(uint32_t d, const void* s) {
    asm volatile("cp.async.cg.shared.global [%0], [%1], 16;" :: "r"(d), "l"(s));
}
__device__ __forceinline__ void cpa_commit() { asm volatile("cp.async.commit_group;" ::: "memory"); }
template<int N> __device__ __forceinline__ void cpa_wait() {
    asm volatile("cp.async.wait_group %0;" :: "n"(N) : "memory");
}
#define LDM4(r, addr) \
    asm volatile("ldmatrix.sync.aligned.m8n8.x4.shared.b16 {%0,%1,%2,%3}, [%4];" \
        : "=r"((r)[0]), "=r"((r)[1]), "=r"((r)[2]), "=r"((r)[3]) : "r"(addr))
#define MMA16816(d, a, b0, b1) \
    asm volatile("mma.sync.aligned.m16n8k16.row.col.f32.bf16.bf16.f32 " \
        "{%0,%1,%2,%3}, {%4,%5,%6,%7}, {%8,%9}, {%0,%1,%2,%3};" \
        : "+f"((d)[0]), "+f"((d)[1]), "+f"((d)[2]), "+f"((d)[3]) \
        : "r"((a)[0]), "r"((a)[1]), "r"((a)[2]), "r"((a)[3]), "r"(b0), "r"(b1))

// ---------------- bf16x3 MMA GEMM: C[M,N] = alpha*(A @ B^T) (+ rowBias) ----------------
// A,B: hi/lo bf16, row-major [rows][K]. BM=BN=128, BK=32, 256 threads (8 warps 2x4),
// warp tile 64x32. Smem: 4 tiles [128][40] bf16 per stage, double-buffered.
#define TILE_B 10240            // 128*40*2 bytes
#define STAGE_B (4*TILE_B)      // 40960
#define GSMEM_TOTAL (2*STAGE_B) // 81920

__global__ void __launch_bounds__(256, 1) gemm_mma3(
    const ushrt* __restrict__ Ah, const ushrt* __restrict__ Al,
    const ushrt* __restrict__ Bh, const ushrt* __restrict__ Bl,
    float* __restrict__ C, int K, int Nc,
    long sA, long sB, long sC,
    const float* __restrict__ bias, float alpha)
{
    extern __shared__ __align__(16) char smem[];
    const int tid = threadIdx.x, wid = tid >> 5, lid = tid & 31;
    const int m0 = blockIdx.y * 128, n0 = blockIdx.x * 128, bz = blockIdx.z;
    const int nk = K >> 5;
    const uint32_t sb = smem_u32(smem);

    const ushrt* gA_h = Ah + (size_t)bz * sA + (size_t)m0 * K;
    const ushrt* gA_l = Al + (size_t)bz * sA + (size_t)m0 * K;
    const ushrt* gB_h = Bh + (size_t)bz * sB + (size_t)n0 * K;
    const ushrt* gB_l = Bl + (size_t)bz * sB + (size_t)n0 * K;
    const ushrt* gsrc[4] = { gA_h, gA_l, gB_h, gB_l };

    // per-thread load mapping: j in 0..7 -> tile=j>>1, row=(j&1)*64 + tid>>2, chunk col = (tid&3)*8
    const int lrow = tid >> 2, lc8 = (tid & 3) * 8;

    // per-thread ldmatrix base offsets (bytes): rows = lid&15, k-half = (lid>>4)*8 elems
    const int wm0 = (wid >> 2) * 64, wn0 = (wid & 3) * 32;
    const uint32_t a_base = sb + (uint32_t)(((wm0 + (lid & 15)) * 40 + (lid >> 4) * 8) * 2);
    const uint32_t b_base = sb + 2 * TILE_B + (uint32_t)(((wn0 + (lid & 15)) * 40 + (lid >> 4) * 8) * 2);

    float acc[4][4][4] = {};

    // prologue: load chunk 0 into stage 0
    {
        const int k0 = 0;
        uint32_t dst0 = sb;
#pragma unroll
        for (int j = 0; j < 8; j++) {
            int tile = j >> 1;
            int row = (j & 1) * 64 + lrow;
            cpa16(dst0 + tile * TILE_B + (uint32_t)((row * 40 + lc8) * 2),
                  gsrc[tile] + (size_t)row * K + k0 + lc8);
        }
        cpa_commit();
    }

    for (int c = 0; c < nk; c++) {
        if (c + 1 < nk) {
            const int k0 = (c + 1) << 5;
            uint32_t dst0 = sb + ((c + 1) & 1) * STAGE_B;
#pragma unroll
            for (int j = 0; j < 8; j++) {
                int tile = j >> 1;
                int row = (j & 1) * 64 + lrow;
                cpa16(dst0 + tile * TILE_B + (uint32_t)((row * 40 + lc8) * 2),
                      gsrc[tile] + (size_t)row * K + k0 + lc8);
            }
            cpa_commit();
            cpa_wait<1>();
        } else {
            cpa_wait<0>();
        }
        __syncthreads();

        const uint32_t st = (c & 1) * STAGE_B;
#pragma unroll
        for (int kk = 0; kk < 2; kk++) {
            const uint32_t koff = st + kk * 32;   // 16 elems * 2 bytes
            uint32_t Ahf[4][4], Alf[4][4], Bhf[2][4], Blf[2][4];
#pragma unroll
            for (int mi = 0; mi < 4; mi++) {
                LDM4(Ahf[mi], a_base + koff + mi * 1280);
                LDM4(Alf[mi], a_base + koff + TILE_B + mi * 1280);
            }
#pragma unroll
            for (int p = 0; p < 2; p++) {
                LDM4(Bhf[p], b_base + koff + p * 1280);
                LDM4(Blf[p], b_base + koff + TILE_B + p * 1280);
            }
#pragma unroll
            for (int mi = 0; mi < 4; mi++) {
#pragma unroll
                for (int nj = 0; nj < 4; nj++) {
                    const int p = nj >> 1, h = nj & 1;
                    MMA16816(acc[mi][nj], Ahf[mi], Bhf[p][h], Bhf[p][h + 2]);
                    MMA16816(acc[mi][nj], Ahf[mi], Blf[p][h], Blf[p][h + 2]);
                    MMA16816(acc[mi][nj], Alf[mi], Bhf[p][h], Bhf[p][h + 2]);
                }
            }
        }
        __syncthreads();
    }

    // epilogue
    const int qr = lid >> 2, qc = (lid & 3) * 2;
    float* Cb = C + (size_t)bz * sC;
#pragma unroll
    for (int mi = 0; mi < 4; mi++) {
        const int row0 = m0 + wm0 + mi * 16 + qr;
        const int row1 = row0 + 8;
        const float bv0 = bias ? bias[row0] : 0.f;
        const float bv1 = bias ? bias[row1] : 0.f;
#pragma unroll
        for (int nj = 0; nj < 4; nj++) {
            const int col = n0 + wn0 + nj * 8 + qc;
            float2 v0, v1;
            v0.x = acc[mi][nj][0] * alpha + bv0;
            v0.y = acc[mi][nj][1] * alpha + bv0;
            v1.x = acc[mi][nj][2] * alpha + bv1;
            v1.y = acc[mi][nj][3] * alpha + bv1;
            *reinterpret_cast<float2*>(Cb + (size_t)row0 * Nc + col) = v0;
            *reinterpret_cast<float2*>(Cb + (size_t)row1 * Nc + col) = v1;
        }
    }
}

// ---------------- pack kernels: fp32 -> bf16 hi/lo (plain row-major) ----------------
__device__ __forceinline__ void split2(float x, ushrt& h, ushrt& l) {
    __nv_bfloat16 bh = __float2bfloat16(x);
    float fh = __bfloat162float(bh);
    __nv_bfloat16 bl = __float2bfloat16(x - fh);
    h = *reinterpret_cast<ushrt*>(&bh);
    l = *reinterpret_cast<ushrt*>(&bl);
}

__global__ __launch_bounds__(256) void pack_split(const float4* __restrict__ X,
                                                  ushort4* __restrict__ H, ushort4* __restrict__ L, long n4)
{
    long i = (long)blockIdx.x * 256 + threadIdx.x;
    if (i >= n4) return;
    float4 v = X[i];
    ushort4 h, l;
    split2(v.x, h.x, l.x); split2(v.y, h.y, l.y);
    split2(v.z, h.z, l.z); split2(v.w, h.w, l.w);
    H[i] = h; L[i] = l;
}

__global__ __launch_bounds__(256) void pack_bn_relu(const float4* __restrict__ X,
                                                    ushort4* __restrict__ H, ushort4* __restrict__ L,
                                                    const float* __restrict__ g, const float* __restrict__ bb)
{
    long i = (long)blockIdx.x * 256 + threadIdx.x;   // over ROWS1*Cc/4
    float4 v = X[i];
    int ch = (int)((i * 4) % Cc);
    v.x = fmaxf(g[ch+0]*(v.x - g_mu1[ch+0])*g_rs1[ch+0] + bb[ch+0], 0.f);
    v.y = fmaxf(g[ch+1]*(v.y - g_mu1[ch+1])*g_rs1[ch+1] + bb[ch+1], 0.f);
    v.z = fmaxf(g[ch+2]*(v.z - g_mu1[ch+2])*g_rs1[ch+2] + bb[ch+2], 0.f);
    v.w = fmaxf(g[ch+3]*(v.w - g_mu1[ch+3])*g_rs1[ch+3] + bb[ch+3], 0.f);
    ushort4 h, l;
    split2(v.x, h.x, l.x); split2(v.y, h.y, l.y);
    split2(v.z, h.z, l.z); split2(v.w, h.w, l.w);
    H[i] = h; L[i] = l;
}

// transpose w[b][t,n] -> wT[b][n,t] packed hi/lo
__global__ __launch_bounds__(256) void pack_transpose_w(ushrt* __restrict__ Hi, ushrt* __restrict__ Lo)
{
    const int bx = blockIdx.x;  // t-chunk (0..7), 64 wide
    const int by = blockIdx.y;  // n-block (0..7), 128 wide
    const int bz = blockIdx.z;  // batch
    __shared__ float s[64][129];
    const float* w = g_attn + (size_t)bz * Tt * Nn;
    const int t0 = bx * 64, n0 = by * 128;
    for (int i = threadIdx.x; i < 64 * 128; i += 256) {
        int t = i >> 7, n = i & 127;
        s[t][n] = w[(size_t)(t0 + t) * Nn + n0 + n];
    }
    __syncthreads();
    for (int i = threadIdx.x; i < 8192; i += 256) {
        int r = i >> 6, cx = i & 63;   // r = n local, cx = t local
        size_t o = ((size_t)(bz * Nn + n0 + r)) * Tt + t0 + cx;
        ushrt h, l;
        split2(s[cx][r], h, l);
        Hi[o] = h; Lo[o] = l;
    }
}

// ---------------- per-(b,t) column: softmax stats + K-th-largest radix select ----------------
__global__ __launch_bounds__(256) void topk_softmax(const float* __restrict__ kvals)
{
    const int b = blockIdx.x >> 9;
    const int t = blockIdx.x & 511;
    float* col = g_attn + ((size_t)b * Tt + t) * Nn;
    const int tid = threadIdx.x;
    __shared__ float sh[8];
    __shared__ unsigned hist[256];
    __shared__ unsigned s_sel, s_rem;

    float x[4]; unsigned u[4];
    float mx = -3.4e38f;
#pragma unroll
    for (int i = 0; i < 4; i++) {
        x[i] = col[tid + 256 * i];
        mx = fmaxf(mx, x[i]);
        unsigned bits = __float_as_uint(x[i]);
        u[i] = (bits & 0x80000000u) ? ~bits : (bits | 0x80000000u);
    }
    for (int o = 16; o > 0; o >>= 1) mx = fmaxf(mx, __shfl_xor_sync(0xffffffffu, mx, o));
    if ((tid & 31) == 0) sh[tid >> 5] = mx;
    __syncthreads();
    if (tid == 0) { float m = sh[0]; for (int i = 1; i < 8; i++) m = fmaxf(m, sh[i]); sh[0] = m; }
    __syncthreads();
    mx = sh[0];
    __syncthreads();
    float s = 0.f;
#pragma unroll
    for (int i = 0; i < 4; i++) s += expf(x[i] - mx);
    for (int o = 16; o > 0; o >>= 1) s += __shfl_xor_sync(0xffffffffu, s, o);
    if ((tid & 31) == 0) sh[tid >> 5] = s;
    __syncthreads();
    if (tid == 0) { float m = 0.f; for (int i = 0; i < 8; i++) m += sh[i]; sh[0] = m; }
    __syncthreads();
    const float inv = 1.f / sh[0];

    int K = (int)rintf((float)Nn * kvals[b]);
    if (K < 0) K = 0;
    if (K > Nn) K = Nn;
    if (K == 0) {
#pragma unroll
        for (int i = 0; i < 4; i++) col[tid + 256 * i] = 0.f;
        return;
    }
    unsigned thr = 0u;
    if (K < Nn) {
        unsigned pref = 0u, rem = (unsigned)K;
        for (int shift = 24; shift >= 0; shift -= 8) {
            hist[tid] = 0u;
            __syncthreads();
            unsigned hm = (shift == 24) ? 0u : (0xFFFFFFFFu << (shift + 8));
#pragma unroll
            for (int i = 0; i < 4; i++)
                if ((u[i] & hm) == pref) atomicAdd(&hist[(u[i] >> shift) & 255u], 1u);
            __syncthreads();
            for (int off = 1; off < 256; off <<= 1) {
                unsigned vv = (tid + off < 256) ? hist[tid + off] : 0u;
                __syncthreads();
                hist[tid] += vv;
                __syncthreads();
            }
            unsigned nxt = (tid < 255) ? hist[tid + 1] : 0u;
            if (hist[tid] >= rem && nxt < rem) { s_sel = (unsigned)tid; s_rem = rem - nxt; }
            __syncthreads();
            pref |= (s_sel << shift);
            rem = s_rem;
            __syncthreads();
        }
        thr = pref;
    }
#pragma unroll
    for (int i = 0; i < 4; i++) {
        float w = (u[i] >= thr) ? expf(x[i] - mx) * inv : 0.f;
        col[tid + 256 * i] = w;
    }
}

// ---------------- BN stats ----------------
__global__ __launch_bounds__(256) void bn_partial(const float* __restrict__ X, float* __restrict__ part)
{
    const int tid = threadIdx.x;
    const float* base = X + (size_t)blockIdx.x * 128 * Cc;
    float s0=0,s1=0,s2=0,q0=0,q1=0,q2=0;
    for (int r = 0; r < 128; r++) {
        const float* row = base + (size_t)r * Cc;
        float a = row[tid], b = row[tid+256], c = row[tid+512];
        s0 += a; q0 = fmaf(a,a,q0);
        s1 += b; q1 = fmaf(b,b,q1);
        s2 += c; q2 = fmaf(c,c,q2);
    }
    float* p = part + (size_t)blockIdx.x * (2*Cc);
    p[tid]    = s0; p[tid+256]    = s1; p[tid+512]    = s2;
    p[Cc+tid] = q0; p[Cc+tid+256] = q1; p[Cc+tid+512] = q2;
}

__global__ void bn_finalize(const float* __restrict__ part, int nblk, float invN,
                            float* __restrict__ mu, float* __restrict__ rs)
{
    int c = blockIdx.x * 256 + threadIdx.x;
    if (c >= Cc) return;
    float s = 0.f, q = 0.f;
    for (int i = 0; i < nblk; i++) {
        s += part[(size_t)i * 2 * Cc + c];
        q += part[(size_t)i * 2 * Cc + Cc + c];
    }
    float m = s * invN;
    mu[c] = m;
    rs[c] = rsqrtf(q * invN - m * m + 1e-5f);
}

__global__ __launch_bounds__(256) void final_apply(float* __restrict__ out, const float* __restrict__ img,
                                                   const float* __restrict__ g, const float* __restrict__ bb)
{
    int i4 = blockIdx.x * 256 + threadIdx.x;
    float4 o = reinterpret_cast<float4*>(out)[i4];
    float4 im = reinterpret_cast<const float4*>(img)[i4];
    int c = (i4 * 4) % Cc;
    o.x = fmaxf(g[c+0]*(o.x - g_mu2[c+0])*g_rs2[c+0] + bb[c+0], 0.f) + im.x;
    o.y = fmaxf(g[c+1]*(o.y - g_mu2[c+1])*g_rs2[c+1] + bb[c+1], 0.f) + im.y;
    o.z = fmaxf(g[c+2]*(o.z - g_mu2[c+2])*g_rs2[c+2] + bb[c+2], 0.f) + im.z;
    o.w = fmaxf(g[c+3]*(o.w - g_mu2[c+3])*g_rs2[c+3] + bb[c+3], 0.f) + im.w;
    reinterpret_cast<float4*>(out)[i4] = o;
}

// ---------------- orchestration ----------------
extern "C" void kernel_launch(void* const* d_in, const int* in_sizes, int n_in,
                              void* d_out, int out_size)
{
    (void)in_sizes; (void)n_in; (void)out_size;
    const float* image = (const float*)d_in[0];
    const float* text  = (const float*)d_in[1];
    const float* kv    = (const float*)d_in[2];
    const float* Wc    = (const float*)d_in[3];
    const float* g1    = (const float*)d_in[5];
    const float* b1    = (const float*)d_in[6];
    const float* Wout  = (const float*)d_in[7];
    const float* bout  = (const float*)d_in[8];
    const float* g2    = (const float*)d_in[9];
    const float* b2    = (const float*)d_in[10];
    float* out = (float*)d_out;

    float *y1, *attn, *vt, *p1, *p2, *mu1, *rs1, *mu2, *rs2;
    ushrt *tx_h, *tx_l, *im_h, *im_l, *wc_h, *wc_l, *wo_h, *wo_l,
          *e1_h, *e1_l, *vt_h, *vt_l, *wt_h, *wt_l;
    cudaGetSymbolAddress((void**)&y1,   g_y1);
    cudaGetSymbolAddress((void**)&attn, g_attn);
    cudaGetSymbolAddress((void**)&vt,   g_vt);
    cudaGetSymbolAddress((void**)&p1,   g_p1);
    cudaGetSymbolAddress((void**)&p2,   g_p2);
    cudaGetSymbolAddress((void**)&mu1,  g_mu1);
    cudaGetSymbolAddress((void**)&rs1,  g_rs1);
    cudaGetSymbolAddress((void**)&mu2,  g_mu2);
    cudaGetSymbolAddress((void**)&rs2,  g_rs2);
    cudaGetSymbolAddress((void**)&tx_h, p_text_hi); cudaGetSymbolAddress((void**)&tx_l, p_text_lo);
    cudaGetSymbolAddress((void**)&im_h, p_img_hi);  cudaGetSymbolAddress((void**)&im_l, p_img_lo);
    cudaGetSymbolAddress((void**)&wc_h, p_Wc_hi);   cudaGetSymbolAddress((void**)&wc_l, p_Wc_lo);
    cudaGetSymbolAddress((void**)&wo_h, p_Wo_hi);   cudaGetSymbolAddress((void**)&wo_l, p_Wo_lo);
    cudaGetSymbolAddress((void**)&e1_h, p_e1_hi);   cudaGetSymbolAddress((void**)&e1_l, p_e1_lo);
    cudaGetSymbolAddress((void**)&vt_h, p_vt_hi);   cudaGetSymbolAddress((void**)&vt_l, p_vt_lo);
    cudaGetSymbolAddress((void**)&wt_h, p_wt_hi);   cudaGetSymbolAddress((void**)&wt_l, p_wt_lo);

    cudaFuncSetAttribute(gemm_mma3, cudaFuncAttributeMaxDynamicSharedMemorySize, GSMEM_TOTAL);

    const float inv_sqrtC = 0.03608439182435161f;  // 1/sqrt(768)

    // pack fp32 -> bf16 hi/lo
    pack_split<<<6144, 256>>>((const float4*)text,  (ushort4*)tx_h, (ushort4*)tx_l, (long)ROWS1*Cc/4);
    pack_split<<<12288, 256>>>((const float4*)image, (ushort4*)im_h, (ushort4*)im_l, (long)ROWS2*Cc/4);
    pack_split<<<576, 256>>>((const float4*)Wc,   (ushort4*)wc_h, (ushort4*)wc_l, (long)Cc*Cc/4);
    pack_split<<<576, 256>>>((const float4*)Wout, (ushort4*)wo_h, (ushort4*)wo_l, (long)Cc*Cc/4);

    // G1: y1[8192,768] = text @ Wc^T   (bias bc cancels inside BN1)
    gemm_mma3<<<dim3(6, 64, 1), 256, GSMEM_TOTAL>>>(
        tx_h, tx_l, wc_h, wc_l, y1, Cc, Cc, 0, 0, 0, nullptr, 1.f);

    // G2: vT[b][768,512] = Wout @ text[b]^T + bout[row]
    gemm_mma3<<<dim3(4, 6, Bb), 256, GSMEM_TOTAL>>>(
        wo_h, wo_l, tx_h, tx_l, vt, Cc, Tt, 0, (long)Tt*Cc, (long)Cc*Tt, bout, 1.f);

    // BN1 stats + fused BN+relu+pack of e1
    bn_partial<<<64, 256>>>(y1, p1);
    bn_finalize<<<3, 256>>>(p1, 64, 1.f/(float)ROWS1, mu1, rs1);
    pack_bn_relu<<<6144, 256>>>((const float4*)y1, (ushort4*)e1_h, (ushort4*)e1_l, g1, b1);

    // pack vT
    pack_split<<<6144, 256>>>((const float4*)vt, (ushort4*)vt_h, (ushort4*)vt_l, (long)Bb*Cc*Tt/4);

    // G3: attn_t[b][512,1024] = (e1[b] @ image[b]^T) / sqrt(C)
    gemm_mma3<<<dim3(8, 4, Bb), 256, GSMEM_TOTAL>>>(
        e1_h, e1_l, im_h, im_l, attn, Cc, Nn,
        (long)Tt*Cc, (long)Nn*Cc, (long)Tt*Nn, nullptr, inv_sqrtC);

    // masked softmax weights in place
    topk_softmax<<<Bb*Tt, 256>>>(kv);

    // transpose + split-pack w -> wT[b][n,t]
    pack_transpose_w<<<dim3(8, 8, Bb), 256>>>(wt_h, wt_l);

    // G4: out_pre[b][1024,768] = wT[b] @ vT[b]^T
    gemm_mma3<<<dim3(6, 8, Bb), 256, GSMEM_TOTAL>>>(
        wt_h, wt_l, vt_h, vt_l, out, Tt, Cc,
        (long)Nn*Tt, (long)Cc*Tt, (long)Nn*Cc, nullptr, 1.f);

    // BN2 + final
    bn_partial<<<128, 256>>>(out, p2);
    bn_finalize<<<3, 256>>>(p2, 128, 1.f/(float)ROWS2, mu2, rs2);
    final_apply<<<12288, 256>>>(out, image, g2, b2);
}